// round 1
// baseline (speedup 1.0000x reference)
#include <cuda_runtime.h>
#include <cstdint>

#define NN 100000
#define F_IN 512
#define HIDDEN 16
#define NCLS 10
#define H2_PAD 12   // h2s row stride (pad 10 -> 12 for float4-aligned gathers)

// ---------------- scratch (no allocation allowed) ----------------
__device__ float g_deg[NN];
__device__ float g_dinv[NN];
__device__ float g_h1s[(size_t)NN * HIDDEN];   // dinv-prescaled layer-1 features
__device__ float g_agg1[(size_t)NN * HIDDEN];  // layer-1 aggregation accumulator
__device__ float g_h2s[(size_t)NN * H2_PAD];   // dinv-prescaled layer-2 features
__device__ int   g_is64;

// ---------------- vector reductions (sm_90+) ----------------
__device__ __forceinline__ void red_add_v4(float* addr, float4 v) {
    asm volatile("red.global.add.v4.f32 [%0], {%1,%2,%3,%4};"
                 :: "l"(addr), "f"(v.x), "f"(v.y), "f"(v.z), "f"(v.w) : "memory");
}
__device__ __forceinline__ void red_add_v2(float* addr, float a, float b) {
    asm volatile("red.global.add.v2.f32 [%0], {%1,%2};"
                 :: "l"(addr), "f"(a), "f"(b) : "memory");
}

// ---------------- edge-index dtype detection ----------------
// If data is int64 (all ids < 2^17), every odd 32-bit word of the first 32
// pairs is zero. If data is int32, those words are random node ids; the
// probability all 32 are zero is ~0.
__global__ void detect_k(const int* __restrict__ ei) {
    int all0 = 1;
    #pragma unroll
    for (int k = 0; k < 32; k++) if (ei[2 * k + 1] != 0) all0 = 0;
    g_is64 = all0;
}

__device__ __forceinline__ void load_edge(const void* ei, long long e, long long E,
                                          int is64, int& src, int& dst) {
    if (is64) {
        const long long* p = (const long long*)ei;
        src = (int)p[e]; dst = (int)p[E + e];
    } else {
        const int* p = (const int*)ei;
        src = p[e]; dst = p[E + e];
    }
}

// ---------------- degree ----------------
__global__ void init_deg_k(int n) {
    int i = blockIdx.x * blockDim.x + threadIdx.x;
    if (i < n) g_deg[i] = 1.0f;  // self-loop
}

__global__ void deg_acc_k(const void* __restrict__ ei, long long E) {
    long long e = (long long)blockIdx.x * blockDim.x + threadIdx.x;
    if (e >= E) return;
    int is64 = g_is64;
    int dst;
    if (is64) dst = (int)((const long long*)ei)[E + e];
    else      dst = ((const int*)ei)[E + e];
    atomicAdd(&g_deg[dst], 1.0f);
}

__global__ void dinv_k(int n) {
    int i = blockIdx.x * blockDim.x + threadIdx.x;
    if (i < n) g_dinv[i] = rsqrtf(g_deg[i]);
}

// ---------------- GEMM1: h1s = (x @ W1) * dinv; agg1 = h1s (self loop) ----------------
#define G1_BLK 128
#define G1_KC 16
__global__ __launch_bounds__(G1_BLK) void gemm1_k(const float* __restrict__ x,
                                                  const float* __restrict__ W1, int n) {
    __shared__ float Ws[F_IN * HIDDEN];    // 32 KB, uniform broadcast reads
    __shared__ float xs[G1_BLK][G1_KC + 1];
    for (int i = threadIdx.x; i < F_IN * HIDDEN; i += G1_BLK) Ws[i] = W1[i];

    int base = blockIdx.x * G1_BLK;
    int node = base + threadIdx.x;
    float acc[HIDDEN];
    #pragma unroll
    for (int j = 0; j < HIDDEN; j++) acc[j] = 0.0f;

    for (int kc = 0; kc < F_IN; kc += G1_KC) {
        __syncthreads();
        #pragma unroll
        for (int i = 0; i < G1_KC; i++) {
            int idx = threadIdx.x + i * G1_BLK;
            int r = idx >> 4, c = idx & 15;
            int nn = base + r;
            xs[r][c] = (nn < n) ? x[(size_t)nn * F_IN + kc + c] : 0.0f;
        }
        __syncthreads();
        #pragma unroll
        for (int c = 0; c < G1_KC; c++) {
            float xv = xs[threadIdx.x][c];
            const float4* w = (const float4*)&Ws[(kc + c) * HIDDEN];
            float4 w0 = w[0], w1 = w[1], w2 = w[2], w3 = w[3];
            acc[0]  = fmaf(xv, w0.x, acc[0]);  acc[1]  = fmaf(xv, w0.y, acc[1]);
            acc[2]  = fmaf(xv, w0.z, acc[2]);  acc[3]  = fmaf(xv, w0.w, acc[3]);
            acc[4]  = fmaf(xv, w1.x, acc[4]);  acc[5]  = fmaf(xv, w1.y, acc[5]);
            acc[6]  = fmaf(xv, w1.z, acc[6]);  acc[7]  = fmaf(xv, w1.w, acc[7]);
            acc[8]  = fmaf(xv, w2.x, acc[8]);  acc[9]  = fmaf(xv, w2.y, acc[9]);
            acc[10] = fmaf(xv, w2.z, acc[10]); acc[11] = fmaf(xv, w2.w, acc[11]);
            acc[12] = fmaf(xv, w3.x, acc[12]); acc[13] = fmaf(xv, w3.y, acc[13]);
            acc[14] = fmaf(xv, w3.z, acc[14]); acc[15] = fmaf(xv, w3.w, acc[15]);
        }
    }
    if (node < n) {
        float di = g_dinv[node];
        float4* h = (float4*)(g_h1s + (size_t)node * HIDDEN);
        float4* a = (float4*)(g_agg1 + (size_t)node * HIDDEN);
        #pragma unroll
        for (int q = 0; q < 4; q++) {
            float4 v = make_float4(acc[4 * q + 0] * di, acc[4 * q + 1] * di,
                                   acc[4 * q + 2] * di, acc[4 * q + 3] * di);
            h[q] = v; a[q] = v;
        }
    }
}

// ---------------- edge scatter layer 1 ----------------
__global__ void edge1_k(const void* __restrict__ ei, long long E) {
    long long e = (long long)blockIdx.x * blockDim.x + threadIdx.x;
    if (e >= E) return;
    int is64 = g_is64;
    int src, dst;
    load_edge(ei, e, E, is64, src, dst);
    const float4* h = (const float4*)(g_h1s + (size_t)src * HIDDEN);
    float4 v0 = h[0], v1 = h[1], v2 = h[2], v3 = h[3];
    float* b = g_agg1 + (size_t)dst * HIDDEN;
    red_add_v4(b + 0, v0);
    red_add_v4(b + 4, v1);
    red_add_v4(b + 8, v2);
    red_add_v4(b + 12, v3);
}

// ---------------- ReLU + GEMM2 (per node), write h2s + self-loop init of out ----------------
__global__ void layer2_k(const float* __restrict__ b1, const float* __restrict__ W2,
                         float* __restrict__ out, int n) {
    __shared__ float W2s[HIDDEN * NCLS];
    __shared__ float b1s[HIDDEN];
    if (threadIdx.x < HIDDEN * NCLS) W2s[threadIdx.x] = W2[threadIdx.x];
    if (threadIdx.x < HIDDEN) b1s[threadIdx.x] = b1[threadIdx.x];
    __syncthreads();
    int node = blockIdx.x * blockDim.x + threadIdx.x;
    if (node >= n) return;
    float di = g_dinv[node];
    const float4* ap = (const float4*)(g_agg1 + (size_t)node * HIDDEN);
    float r[HIDDEN];
    #pragma unroll
    for (int q = 0; q < 4; q++) {
        float4 a = ap[q];
        r[4 * q + 0] = fmaxf(fmaf(a.x, di, b1s[4 * q + 0]), 0.0f);
        r[4 * q + 1] = fmaxf(fmaf(a.y, di, b1s[4 * q + 1]), 0.0f);
        r[4 * q + 2] = fmaxf(fmaf(a.z, di, b1s[4 * q + 2]), 0.0f);
        r[4 * q + 3] = fmaxf(fmaf(a.w, di, b1s[4 * q + 3]), 0.0f);
    }
    float o[NCLS];
    #pragma unroll
    for (int c = 0; c < NCLS; c++) o[c] = 0.0f;
    #pragma unroll
    for (int j = 0; j < HIDDEN; j++) {
        float rv = r[j];
        #pragma unroll
        for (int c = 0; c < NCLS; c++) o[c] = fmaf(rv, W2s[j * NCLS + c], o[c]);
    }
    float* h2 = g_h2s + (size_t)node * H2_PAD;
    float* ob = out + (size_t)node * NCLS;
    #pragma unroll
    for (int c = 0; c < NCLS; c++) {
        float v = o[c] * di;
        h2[c] = v;
        ob[c] = v;  // self-loop contribution; also initializes poisoned d_out
    }
}

// ---------------- edge scatter layer 2 (into d_out) ----------------
__global__ void edge2_k(const void* __restrict__ ei, long long E, float* __restrict__ out) {
    long long e = (long long)blockIdx.x * blockDim.x + threadIdx.x;
    if (e >= E) return;
    int is64 = g_is64;
    int src, dst;
    load_edge(ei, e, E, is64, src, dst);
    const float* h = g_h2s + (size_t)src * H2_PAD;
    float4 f0 = *(const float4*)(h);
    float4 f1 = *(const float4*)(h + 4);
    float2 f2 = *(const float2*)(h + 8);
    float* b = out + (size_t)dst * NCLS;
    red_add_v2(b + 0, f0.x, f0.y);
    red_add_v2(b + 2, f0.z, f0.w);
    red_add_v2(b + 4, f1.x, f1.y);
    red_add_v2(b + 6, f1.z, f1.w);
    red_add_v2(b + 8, f2.x, f2.y);
}

// ---------------- final: out = out*dinv[dst] + b2 ----------------
__global__ void final_k(float* __restrict__ out, const float* __restrict__ b2, int n) {
    int i = blockIdx.x * blockDim.x + threadIdx.x;
    if (i >= n * NCLS) return;
    int node = i / NCLS;
    int c = i - node * NCLS;
    out[i] = fmaf(out[i], g_dinv[node], b2[c]);
}

// ---------------- launch ----------------
extern "C" void kernel_launch(void* const* d_in, const int* in_sizes, int n_in,
                              void* d_out, int out_size) {
    const float* x  = (const float*)d_in[0];
    const void*  ei = d_in[1];
    const float* W1 = (const float*)d_in[2];
    const float* b1 = (const float*)d_in[3];
    const float* W2 = (const float*)d_in[4];
    const float* b2 = (const float*)d_in[5];
    float* out = (float*)d_out;

    int n = in_sizes[0] / F_IN;                 // 100000
    long long E = (long long)in_sizes[1] / 2;   // 3200000 (elem count same for i32/i64)

    int nb_n   = (n + 255) / 256;
    int nb_e   = (int)((E + 255) / 256);
    int nb_g1  = (n + G1_BLK - 1) / G1_BLK;
    int nb_out = (n * NCLS + 255) / 256;

    detect_k<<<1, 1>>>((const int*)ei);
    init_deg_k<<<nb_n, 256>>>(n);
    deg_acc_k<<<nb_e, 256>>>(ei, E);
    dinv_k<<<nb_n, 256>>>(n);
    gemm1_k<<<nb_g1, G1_BLK>>>(x, W1, n);
    edge1_k<<<nb_e, 256>>>(ei, E);
    layer2_k<<<nb_n, 256>>>(b1, W2, out, n);
    edge2_k<<<nb_e, 256>>>(ei, E, out);
    final_k<<<nb_out, 256>>>(out, b2, n);
}